// round 8
// baseline (speedup 1.0000x reference)
#include <cuda_runtime.h>
#include <cuda_fp16.h>
#include <cstdint>
#include <math.h>

#define NTOK 4096
#define HDIM 4096
#define FDIM 14336
#define NEXP 8
#define NR   8
#define LSCALE 2.0f

// ---------------------------------------------------------------------------
// Scratch (__device__ globals; allocation-free rule)
// ---------------------------------------------------------------------------
__device__ __half g_xh[(size_t)NTOK * HDIM];   // x as fp16 [N,H]
__device__ __half g_b1[(size_t)FDIM * HDIM];   // w1^T [F,H] fp16
__device__ __half g_b3[(size_t)FDIM * HDIM];   // w3^T [F,H] fp16
__device__ __half g_b2[(size_t)HDIM * FDIM];   // w2^T [H,F] fp16
__device__ __half g_a2[(size_t)NTOK * FDIM];   // silu(gate)*up fp16 [N,F]
__device__ float  g_c[NTOK * NEXP * NR];       // LoRA coefficients

// ---------------------------------------------------------------------------
// Asm helpers (sm_80-level features; legal on plain sm_103 target)
// ---------------------------------------------------------------------------
__device__ __forceinline__ uint32_t smem_u32(const void* p) {
    uint32_t a;
    asm("{ .reg .u64 t; cvta.to.shared.u64 t, %1; cvt.u32.u64 %0, t; }" : "=r"(a) : "l"(p));
    return a;
}

#define CP16(dst, src) \
    asm volatile("cp.async.cg.shared.global [%0], [%1], 16;" :: "r"(dst), "l"(src))
#define CP_COMMIT() asm volatile("cp.async.commit_group;" ::: "memory")
#define CP_WAIT1()  asm volatile("cp.async.wait_group 1;" ::: "memory")

#define LDSM4(r0, r1, r2, r3, a) \
    asm volatile("ldmatrix.sync.aligned.m8n8.x4.shared.b16 {%0,%1,%2,%3}, [%4];" \
        : "=r"(r0), "=r"(r1), "=r"(r2), "=r"(r3) : "r"(a))

#define MMA_F16(c, a0, a1, a2, a3, b0, b1) \
    asm volatile("mma.sync.aligned.m16n8k16.row.col.f32.f16.f16.f32 " \
        "{%0,%1,%2,%3}, {%4,%5,%6,%7}, {%8,%9}, {%0,%1,%2,%3};" \
        : "+f"((c)[0]), "+f"((c)[1]), "+f"((c)[2]), "+f"((c)[3]) \
        : "r"(a0), "r"(a1), "r"(a2), "r"(a3), "r"(b0), "r"(b1))

// ---------------------------------------------------------------------------
// Conversion kernels
// ---------------------------------------------------------------------------
__global__ void __launch_bounds__(256) convert_x_kernel(const float* __restrict__ x) {
    size_t n = (size_t)NTOK * HDIM;
    size_t stride = (size_t)gridDim.x * blockDim.x * 4;
    for (size_t i = ((size_t)blockIdx.x * blockDim.x + threadIdx.x) * 4; i < n; i += stride) {
        float4 v = *(const float4*)(x + i);
        *(__half2*)(g_xh + i)     = __floats2half2_rn(v.x, v.y);
        *(__half2*)(g_xh + i + 2) = __floats2half2_rn(v.z, v.w);
    }
}

// W [K,N] fp32 -> [N,K] fp16, 64k x 32n tiles, half2-coalesced writes
__global__ void __launch_bounds__(256) transpose_convert_kernel(
    const float* __restrict__ W, __half* __restrict__ out, int K, int N)
{
    __shared__ float t[64][33];
    int n0 = blockIdx.x * 32, k0 = blockIdx.y * 64;
    int tx = threadIdx.x & 31, ty = threadIdx.x >> 5;   // 32 x 8
    #pragma unroll
    for (int j = 0; j < 8; j++)
        t[ty + 8 * j][tx] = W[(size_t)(k0 + ty + 8 * j) * N + n0 + tx];
    __syncthreads();
    #pragma unroll
    for (int j = 0; j < 4; j++) {
        int n = ty + 8 * j;     // 0..31
        __half2 h = __floats2half2_rn(t[2 * tx][n], t[2 * tx + 1][n]);
        *(__half2*)(out + (size_t)(n0 + n) * K + k0 + 2 * tx) = h;
    }
}

// ---------------------------------------------------------------------------
// Router + LoRA coefficients
// ---------------------------------------------------------------------------
__global__ void __launch_bounds__(128) router_lora_kernel(
    const float* __restrict__ x, const float* __restrict__ router_w,
    const float* __restrict__ lora_A, float* __restrict__ logits_out)
{
    int n = blockIdx.x;
    __shared__ float xs[HDIM];
    __shared__ float logits[NEXP];
    __shared__ int   sel[2];
    __shared__ float rws[2];

    const float* xr = x + (size_t)n * HDIM;
    for (int i = threadIdx.x; i < HDIM / 4; i += blockDim.x)
        ((float4*)xs)[i] = ((const float4*)xr)[i];
    __syncthreads();

    int wid = threadIdx.x >> 5, lane = threadIdx.x & 31;
    for (int e = wid; e < NEXP; e += 4) {
        const float* wr = router_w + (size_t)e * HDIM;
        float s = 0.f;
        for (int h = lane; h < HDIM; h += 32) s += xs[h] * wr[h];
        #pragma unroll
        for (int o = 16; o; o >>= 1) s += __shfl_down_sync(0xffffffffu, s, o);
        if (lane == 0) {
            logits[e] = s;
            if (logits_out) logits_out[(size_t)n * NEXP + e] = s;
        }
    }
    __syncthreads();

    if (threadIdx.x == 0) {
        float m = -1e30f;
        for (int e = 0; e < NEXP; e++) m = fmaxf(m, logits[e]);
        float p[NEXP];
        for (int e = 0; e < NEXP; e++) p[e] = expf(logits[e] - m);
        int i0 = 0;
        for (int e = 1; e < NEXP; e++) if (p[e] > p[i0]) i0 = e;
        int i1 = -1;
        for (int e = 0; e < NEXP; e++) {
            if (e == i0) continue;
            if (i1 < 0 || p[e] > p[i1]) i1 = e;
        }
        float s2 = p[i0] + p[i1];
        sel[0] = i0; sel[1] = i1;
        rws[0] = p[i0] / s2; rws[1] = p[i1] / s2;
    }
    if (threadIdx.x < NEXP * NR) g_c[n * NEXP * NR + threadIdx.x] = 0.f;
    __syncthreads();

    int p  = threadIdx.x >> 3;
    int l8 = threadIdx.x & 7;
    int k  = p >> 3;
    int r  = p & 7;
    int e  = sel[k];
    const float* A = lora_A + (size_t)e * HDIM * NR + r;
    float s = 0.f;
    for (int h = l8; h < HDIM; h += 8) s += xs[h] * A[(size_t)h * NR];
    s += __shfl_down_sync(0xffffffffu, s, 4);
    s += __shfl_down_sync(0xffffffffu, s, 2);
    s += __shfl_down_sync(0xffffffffu, s, 1);
    if (l8 == 0) g_c[n * NEXP * NR + e * NR + r] = rws[k] * LSCALE * s;
}

// ---------------------------------------------------------------------------
// Small fp32 SGEMM for LoRA (K=64), writes out with beta=0
// ---------------------------------------------------------------------------
__global__ void __launch_bounds__(256) sgemm128_kernel(
    const float* __restrict__ A, const float* __restrict__ B,
    float* __restrict__ C, int M, int N, int K)
{
    __shared__ float As[8][128];
    __shared__ float Bs[8][128];
    int tid = threadIdx.x;
    int m0 = blockIdx.y * 128, n0 = blockIdx.x * 128;
    int aRow = tid >> 1, aCol = (tid & 1) * 4;
    int bRow = tid >> 5, bCol = (tid & 31) * 4;
    const float* Aptr = A + (size_t)(m0 + aRow) * K + aCol;
    const float* Bptr = B + (size_t)bRow * N + n0 + bCol;
    int ty = tid >> 4, tx = tid & 15;

    float acc[8][8];
    #pragma unroll
    for (int i = 0; i < 8; i++)
        #pragma unroll
        for (int j = 0; j < 8; j++) acc[i][j] = 0.f;

    for (int k0 = 0; k0 < K; k0 += 8) {
        float4 av = *(const float4*)Aptr; Aptr += 8;
        float4 bv = *(const float4*)Bptr; Bptr += (size_t)8 * N;
        As[aCol + 0][aRow] = av.x; As[aCol + 1][aRow] = av.y;
        As[aCol + 2][aRow] = av.z; As[aCol + 3][aRow] = av.w;
        *(float4*)&Bs[bRow][bCol] = bv;
        __syncthreads();
        #pragma unroll
        for (int kk = 0; kk < 8; kk++) {
            float a[8], b[8];
            *(float4*)(a)     = *(const float4*)&As[kk][ty * 8];
            *(float4*)(a + 4) = *(const float4*)&As[kk][ty * 8 + 4];
            *(float4*)(b)     = *(const float4*)&Bs[kk][tx * 8];
            *(float4*)(b + 4) = *(const float4*)&Bs[kk][tx * 8 + 4];
            #pragma unroll
            for (int i = 0; i < 8; i++)
                #pragma unroll
                for (int j = 0; j < 8; j++)
                    acc[i][j] = fmaf(a[i], b[j], acc[i][j]);
        }
        __syncthreads();
    }
    #pragma unroll
    for (int i = 0; i < 8; i++) {
        float* Cr = C + (size_t)(m0 + ty * 8 + i) * N + n0 + tx * 8;
        *(float4*)Cr       = make_float4(acc[i][0], acc[i][1], acc[i][2], acc[i][3]);
        *(float4*)(Cr + 4) = make_float4(acc[i][4], acc[i][5], acc[i][6], acc[i][7]);
    }
}

// ---------------------------------------------------------------------------
// FUSED gate+up GEMM, 128m x 64n CTA tile (occ=2).
// Stage 32KB: A rows 0-127, B1 rows 128-191, B3 rows 192-255.
// Epilogue: a2 = fp16(silu(gate) * up). Raster: groups of 8 n-tiles.
// ---------------------------------------------------------------------------
#define FSTG 32768
#define FUSED_SMEM (3 * FSTG)

__device__ __forceinline__ void issue_stage_gu(
    uint32_t st, const __half* A, const __half* B1, const __half* B3,
    int m0, int n0, int kpos, int K, int lr, int lkc)
{
    #pragma unroll
    for (int rr = 0; rr < 256; rr += 32) {
        int row = lr + rr;
        uint32_t so = row * 128 + ((lkc ^ (row & 7)) << 4);
        const __half* src;
        if (rr < 128)      src = A  + (size_t)(m0 + row) * K;
        else if (rr < 192) src = B1 + (size_t)(n0 + row - 128) * K;
        else               src = B3 + (size_t)(n0 + row - 192) * K;
        CP16(st + so, src + kpos + lkc * 8);
    }
    CP_COMMIT();
}

__global__ void __launch_bounds__(256, 2) gemm_gateup_kernel(
    const __half* __restrict__ A, const __half* __restrict__ B1,
    const __half* __restrict__ B3, __half* __restrict__ oA2, int K)
{
    extern __shared__ __align__(1024) char smem[];
    uint32_t sb = smem_u32(smem);
    int tid = threadIdx.x;
    int wid = tid >> 5, lane = tid & 31;
    int wm = wid >> 2, wn = wid & 3;

    int lin = blockIdx.y * gridDim.x + blockIdx.x;
    int gs  = 8 * gridDim.y;
    int g   = lin / gs, r = lin - g * gs;
    int m0  = (r >> 3) * 128;
    int n0  = (g * 8 + (r & 7)) * 64;

    int NT = K >> 6;
    int lr = tid >> 3, lkc = tid & 7;

    int laneM  = lane & 15;
    int kHalfA = lane >> 4;
    int aSw    = laneM & 7;
    uint32_t rowOffA[4];
    #pragma unroll
    for (int tm = 0; tm < 4; tm++)
        rowOffA[tm] = (uint32_t)(wm * 64 + tm * 16 + laneM) * 128;
    int l7     = lane & 7;
    int kHalfB = (lane >> 3) & 1;
    uint32_t rowB = (uint32_t)(wn * 16 + ((lane >> 4) & 1) * 8 + l7) * 128;

    float accG[4][2][4], accU[4][2][4];
    #pragma unroll
    for (int i = 0; i < 4; i++)
        #pragma unroll
        for (int j = 0; j < 2; j++)
            #pragma unroll
            for (int q = 0; q < 4; q++) { accG[i][j][q] = 0.f; accU[i][j][q] = 0.f; }

    issue_stage_gu(sb,        A, B1, B3, m0, n0, 0,  K, lr, lkc);
    issue_stage_gu(sb + FSTG, A, B1, B3, m0, n0, 64, K, lr, lkc);

    for (int kt = 0; kt < NT; kt++) {
        CP_WAIT1();
        __syncthreads();
        if (kt + 2 < NT)
            issue_stage_gu(sb + ((kt + 2) % 3) * FSTG, A, B1, B3,
                           m0, n0, (kt + 2) << 6, K, lr, lkc);
        else
            CP_COMMIT();

        uint32_t st = sb + (kt % 3) * FSTG;
        #pragma unroll
        for (int kk = 0; kk < 4; kk++) {
            uint32_t ah[4][4], b1f[4], b3f[4];
            uint32_t chA = (uint32_t)(((kk * 2 + kHalfA) ^ aSw) << 4);
            #pragma unroll
            for (int tm = 0; tm < 4; tm++)
                LDSM4(ah[tm][0], ah[tm][1], ah[tm][2], ah[tm][3], st + rowOffA[tm] + chA);
            uint32_t chB = (uint32_t)(((kk * 2 + kHalfB) ^ l7) << 4);
            LDSM4(b1f[0], b1f[1], b1f[2], b1f[3], st + 16384 + rowB + chB);
            LDSM4(b3f[0], b3f[1], b3f[2], b3f[3], st + 24576 + rowB + chB);
            #pragma unroll
            for (int tm = 0; tm < 4; tm++)
                #pragma unroll
                for (int tn = 0; tn < 2; tn++) {
                    MMA_F16(accG[tm][tn], ah[tm][0], ah[tm][1], ah[tm][2], ah[tm][3],
                            b1f[2 * tn], b1f[2 * tn + 1]);
                    MMA_F16(accU[tm][tn], ah[tm][0], ah[tm][1], ah[tm][2], ah[tm][3],
                            b3f[2 * tn], b3f[2 * tn + 1]);
                }
        }
    }

    int g2 = lane >> 2, q2 = (lane & 3) * 2;
    size_t Nt = (size_t)gridDim.x * 64;
    #pragma unroll
    for (int tm = 0; tm < 4; tm++) {
        #pragma unroll
        for (int tn = 0; tn < 2; tn++) {
            int mg = m0 + wm * 64 + tm * 16 + g2;
            int cg = n0 + wn * 16 + tn * 8 + q2;
            size_t o0 = (size_t)mg * Nt + cg;
            size_t o1 = o0 + 8 * Nt;
            float* gg = accG[tm][tn];
            float* uu = accU[tm][tn];
            float v0 = gg[0] / (1.f + __expf(-gg[0])) * uu[0];
            float v1 = gg[1] / (1.f + __expf(-gg[1])) * uu[1];
            float v2 = gg[2] / (1.f + __expf(-gg[2])) * uu[2];
            float v3 = gg[3] / (1.f + __expf(-gg[3])) * uu[3];
            *(__half2*)(oA2 + o0) = __floats2half2_rn(v0, v1);
            *(__half2*)(oA2 + o1) = __floats2half2_rn(v2, v3);
        }
    }
}

// ---------------------------------------------------------------------------
// Down-projection fp16 GEMM: C += A @ B^T, 128m x 64n tile (occ=2, low tail).
// Stage 24KB: A rows 0-127, B rows 128-191. Raster: groups of 8 n-tiles.
// ---------------------------------------------------------------------------
#define DSTG 24576
#define DOWN_SMEM (3 * DSTG)

__device__ __forceinline__ void issue_stage_dn(
    uint32_t st, const __half* A, const __half* B,
    int m0, int n0, int kpos, int K, int lr, int lkc)
{
    #pragma unroll
    for (int rr = 0; rr < 192; rr += 32) {
        int row = lr + rr;
        uint32_t so = row * 128 + ((lkc ^ (row & 7)) << 4);
        const __half* src = (rr < 128) ? A + (size_t)(m0 + row) * K
                                       : B + (size_t)(n0 + row - 128) * K;
        CP16(st + so, src + kpos + lkc * 8);
    }
    CP_COMMIT();
}

__global__ void __launch_bounds__(256, 2) gemm_down_kernel(
    const __half* __restrict__ A, const __half* __restrict__ B,
    float* __restrict__ C, int K)
{
    extern __shared__ __align__(1024) char smem[];
    uint32_t sb = smem_u32(smem);
    int tid = threadIdx.x;
    int wid = tid >> 5, lane = tid & 31;
    int wm = wid >> 2, wn = wid & 3;

    int lin = blockIdx.y * gridDim.x + blockIdx.x;
    int gs  = 8 * gridDim.y;
    int g   = lin / gs, r = lin - g * gs;
    int m0  = (r >> 3) * 128;
    int n0  = (g * 8 + (r & 7)) * 64;

    int NT = K >> 6;
    int lr = tid >> 3, lkc = tid & 7;

    int laneM  = lane & 15;
    int kHalfA = lane >> 4;
    int aSw    = laneM & 7;
    uint32_t rowOffA[4];
    #pragma unroll
    for (int tm = 0; tm < 4; tm++)
        rowOffA[tm] = (uint32_t)(wm * 64 + tm * 16 + laneM) * 128;
    int l7     = lane & 7;
    int kHalfB = (lane >> 3) & 1;
    uint32_t rowB = (uint32_t)(wn * 16 + ((lane >> 4) & 1) * 8 + l7) * 128;

    float acc[4][2][4];
    #pragma unroll
    for (int i = 0; i < 4; i++)
        #pragma unroll
        for (int j = 0; j < 2; j++)
            #pragma unroll
            for (int q = 0; q < 4; q++) acc[i][j][q] = 0.f;

    issue_stage_dn(sb,        A, B, m0, n0, 0,  K, lr, lkc);
    issue_stage_dn(sb + DSTG, A, B, m0, n0, 64, K, lr, lkc);

    for (int kt = 0; kt < NT; kt++) {
        CP_WAIT1();
        __syncthreads();
        if (kt + 2 < NT)
            issue_stage_dn(sb + ((kt + 2) % 3) * DSTG, A, B,
                           m0, n0, (kt + 2) << 6, K, lr, lkc);
        else
            CP_COMMIT();

        uint32_t st = sb + (kt % 3) * DSTG;
        #pragma unroll
        for (int kk = 0; kk < 4; kk++) {
            uint32_t ah[4][4], bf[4];
            uint32_t chA = (uint32_t)(((kk * 2 + kHalfA) ^ aSw) << 4);
            #pragma unroll
            for (int tm = 0; tm < 4; tm++)
                LDSM4(ah[tm][0], ah[tm][1], ah[tm][2], ah[tm][3], st + rowOffA[tm] + chA);
            uint32_t chB = (uint32_t)(((kk * 2 + kHalfB) ^ l7) << 4);
            LDSM4(bf[0], bf[1], bf[2], bf[3], st + 16384 + rowB + chB);
            #pragma unroll
            for (int tm = 0; tm < 4; tm++)
                #pragma unroll
                for (int tn = 0; tn < 2; tn++)
                    MMA_F16(acc[tm][tn], ah[tm][0], ah[tm][1], ah[tm][2], ah[tm][3],
                            bf[2 * tn], bf[2 * tn + 1]);
        }
    }

    int g2 = lane >> 2, q2 = (lane & 3) * 2;
    size_t Nt = (size_t)gridDim.x * 64;
    #pragma unroll
    for (int tm = 0; tm < 4; tm++) {
        #pragma unroll
        for (int tn = 0; tn < 2; tn++) {
            int mg = m0 + wm * 64 + tm * 16 + g2;
            int cg = n0 + wn * 16 + tn * 8 + q2;
            size_t o0 = (size_t)mg * Nt + cg;
            size_t o1 = o0 + 8 * Nt;
            float* a = acc[tm][tn];
            float2 c0 = *(const float2*)(C + o0);
            float2 c1 = *(const float2*)(C + o1);
            c0.x += a[0]; c0.y += a[1];
            c1.x += a[2]; c1.y += a[3];
            *(float2*)(C + o0) = c0;
            *(float2*)(C + o1) = c1;
        }
    }
}

// ---------------------------------------------------------------------------
extern "C" void kernel_launch(void* const* d_in, const int* in_sizes, int n_in,
                              void* d_out, int out_size)
{
    const float* x        = (const float*)d_in[0];
    const float* router_w = (const float*)d_in[1];
    const float* w1       = (const float*)d_in[2];
    const float* w2       = (const float*)d_in[3];
    const float* w3       = (const float*)d_in[4];
    const float* lora_A   = (const float*)d_in[5];
    const float* lora_B   = (const float*)d_in[6];
    float* out = (float*)d_out;

    static bool init_done = false;
    static float *cc;
    static __half *xh, *b1, *b3, *b2, *a2;
    static cudaStream_t s2 = 0;
    static cudaEvent_t evRoot = 0, evJoin = 0;
    if (!init_done) {
        cudaGetSymbolAddress((void**)&cc, g_c);
        cudaGetSymbolAddress((void**)&xh, g_xh);
        cudaGetSymbolAddress((void**)&b1, g_b1);
        cudaGetSymbolAddress((void**)&b3, g_b3);
        cudaGetSymbolAddress((void**)&b2, g_b2);
        cudaGetSymbolAddress((void**)&a2, g_a2);
        cudaFuncSetAttribute(gemm_gateup_kernel,
                             cudaFuncAttributeMaxDynamicSharedMemorySize, FUSED_SMEM);
        cudaFuncSetAttribute(gemm_down_kernel,
                             cudaFuncAttributeMaxDynamicSharedMemorySize, DOWN_SMEM);
        if (cudaStreamCreateWithFlags(&s2, cudaStreamNonBlocking) != cudaSuccess) s2 = 0;
        if (cudaEventCreateWithFlags(&evRoot, cudaEventDisableTiming) != cudaSuccess) evRoot = 0;
        if (cudaEventCreateWithFlags(&evJoin, cudaEventDisableTiming) != cudaSuccess) evJoin = 0;
        if (!evRoot || !evJoin) s2 = 0;   // no fork without events
        init_done = true;
    }

    float* logits_out = nullptr;
    if ((size_t)out_size >= (size_t)NTOK * HDIM + (size_t)NTOK * NEXP)
        logits_out = out + (size_t)NTOK * HDIM;

    // ---- fork: independent prep on s2 (w2 transpose, router, LoRA init of out)
    if (s2) {
        cudaEventRecord(evRoot, 0);
        cudaStreamWaitEvent(s2, evRoot, 0);
    }
    cudaStream_t sideStream = s2 ? s2 : 0;
    transpose_convert_kernel<<<dim3(HDIM / 32, FDIM / 64), 256, 0, sideStream>>>(w2, b2, FDIM, HDIM);
    router_lora_kernel<<<NTOK, 128, 0, sideStream>>>(x, router_w, lora_A, logits_out);
    sgemm128_kernel<<<dim3(HDIM / 128, NTOK / 128), 256, 0, sideStream>>>(
        cc, lora_B, out, NTOK, HDIM, NEXP * NR);
    if (s2) cudaEventRecord(evJoin, s2);

    // ---- main stream: gate+up path
    convert_x_kernel<<<4096, 256>>>(x);
    transpose_convert_kernel<<<dim3(FDIM / 32, HDIM / 64), 256>>>(w1, b1, HDIM, FDIM);
    transpose_convert_kernel<<<dim3(FDIM / 32, HDIM / 64), 256>>>(w3, b3, HDIM, FDIM);
    gemm_gateup_kernel<<<dim3(FDIM / 64, NTOK / 128), 256, FUSED_SMEM>>>(
        xh, b1, b3, a2, HDIM);

    // ---- join, then down-proj accumulates onto out
    if (s2) cudaStreamWaitEvent(0, evJoin, 0);
    gemm_down_kernel<<<dim3(HDIM / 64, NTOK / 128), 256, DOWN_SMEM>>>(
        a2, b2, out, FDIM);
}

// round 9
// speedup vs baseline: 1.6358x; 1.6358x over previous
#include <cuda_runtime.h>
#include <cuda_fp16.h>
#include <cstdint>
#include <math.h>

#define NTOK 4096
#define HDIM 4096
#define FDIM 14336
#define NEXP 8
#define NR   8
#define LSCALE 2.0f

// ---------------------------------------------------------------------------
// Scratch (__device__ globals; allocation-free rule)
// ---------------------------------------------------------------------------
__device__ __half g_xh[(size_t)NTOK * HDIM];   // x as fp16 [N,H]
__device__ __half g_b1[(size_t)FDIM * HDIM];   // w1^T [F,H] fp16
__device__ __half g_b3[(size_t)FDIM * HDIM];   // w3^T [F,H] fp16
__device__ __half g_b2[(size_t)HDIM * FDIM];   // w2^T [H,F] fp16
__device__ __half g_a2[(size_t)NTOK * FDIM];   // silu(gate)*up fp16 [N,F]
__device__ float  g_c[NTOK * NEXP * NR];       // LoRA coefficients

// ---------------------------------------------------------------------------
// Asm helpers (sm_80-level features; legal on plain sm_103 target)
// ---------------------------------------------------------------------------
__device__ __forceinline__ uint32_t smem_u32(const void* p) {
    uint32_t a;
    asm("{ .reg .u64 t; cvta.to.shared.u64 t, %1; cvt.u32.u64 %0, t; }" : "=r"(a) : "l"(p));
    return a;
}

#define CP16(dst, src) \
    asm volatile("cp.async.cg.shared.global [%0], [%1], 16;" :: "r"(dst), "l"(src))
#define CP_COMMIT() asm volatile("cp.async.commit_group;" ::: "memory")
#define CP_WAIT1()  asm volatile("cp.async.wait_group 1;" ::: "memory")

#define LDSM4(r0, r1, r2, r3, a) \
    asm volatile("ldmatrix.sync.aligned.m8n8.x4.shared.b16 {%0,%1,%2,%3}, [%4];" \
        : "=r"(r0), "=r"(r1), "=r"(r2), "=r"(r3) : "r"(a))

#define MMA_F16(c, a0, a1, a2, a3, b0, b1) \
    asm volatile("mma.sync.aligned.m16n8k16.row.col.f32.f16.f16.f32 " \
        "{%0,%1,%2,%3}, {%4,%5,%6,%7}, {%8,%9}, {%0,%1,%2,%3};" \
        : "+f"((c)[0]), "+f"((c)[1]), "+f"((c)[2]), "+f"((c)[3]) \
        : "r"(a0), "r"(a1), "r"(a2), "r"(a3), "r"(b0), "r"(b1))

// ---------------------------------------------------------------------------
// Merged transpose: one launch converts w1,w3,w2 (fp32 [K,N] -> fp16 [N,K]).
// All three have exactly (N/32)*(K/64) = 28672 blocks. blockIdx.y selects.
// ---------------------------------------------------------------------------
__global__ void __launch_bounds__(256) transpose_all_kernel(
    const float* __restrict__ w1, const float* __restrict__ w3,
    const float* __restrict__ w2,
    __half* __restrict__ b1, __half* __restrict__ b3, __half* __restrict__ b2)
{
    const float* W;
    __half* out;
    int K, N, nBlk;
    if (blockIdx.y == 0)      { W = w1; out = b1; K = HDIM; N = FDIM; nBlk = FDIM / 32; }
    else if (blockIdx.y == 1) { W = w3; out = b3; K = HDIM; N = FDIM; nBlk = FDIM / 32; }
    else                      { W = w2; out = b2; K = FDIM; N = HDIM; nBlk = HDIM / 32; }

    int b  = blockIdx.x;
    int n0 = (b % nBlk) * 32;
    int k0 = (b / nBlk) * 64;

    __shared__ float t[64][33];
    int tx = threadIdx.x & 31, ty = threadIdx.x >> 5;   // 32 x 8
    #pragma unroll
    for (int j = 0; j < 8; j++)
        t[ty + 8 * j][tx] = W[(size_t)(k0 + ty + 8 * j) * N + n0 + tx];
    __syncthreads();
    #pragma unroll
    for (int j = 0; j < 4; j++) {
        int n = ty + 8 * j;     // 0..31
        __half2 h = __floats2half2_rn(t[2 * tx][n], t[2 * tx + 1][n]);
        *(__half2*)(out + (size_t)(n0 + n) * K + k0 + 2 * tx) = h;
    }
}

// ---------------------------------------------------------------------------
// Router + LoRA coefficients + x fp16 conversion (folded)
// ---------------------------------------------------------------------------
__global__ void __launch_bounds__(128) router_lora_kernel(
    const float* __restrict__ x, const float* __restrict__ router_w,
    const float* __restrict__ lora_A, float* __restrict__ logits_out)
{
    int n = blockIdx.x;
    __shared__ float xs[HDIM];
    __shared__ float logits[NEXP];
    __shared__ int   sel[2];
    __shared__ float rws[2];

    const float* xr = x + (size_t)n * HDIM;
    for (int i = threadIdx.x; i < HDIM / 4; i += blockDim.x)
        ((float4*)xs)[i] = ((const float4*)xr)[i];
    __syncthreads();

    // fp16 conversion of x (replaces convert_x_kernel; same rounding intrinsic)
    {
        __half* xo = g_xh + (size_t)n * HDIM;
        for (int i = threadIdx.x; i < HDIM / 2; i += blockDim.x)
            *(__half2*)(xo + 2 * i) = __floats2half2_rn(xs[2 * i], xs[2 * i + 1]);
    }

    int wid = threadIdx.x >> 5, lane = threadIdx.x & 31;
    for (int e = wid; e < NEXP; e += 4) {
        const float* wr = router_w + (size_t)e * HDIM;
        float s = 0.f;
        for (int h = lane; h < HDIM; h += 32) s += xs[h] * wr[h];
        #pragma unroll
        for (int o = 16; o; o >>= 1) s += __shfl_down_sync(0xffffffffu, s, o);
        if (lane == 0) {
            logits[e] = s;
            if (logits_out) logits_out[(size_t)n * NEXP + e] = s;
        }
    }
    __syncthreads();

    if (threadIdx.x == 0) {
        float m = -1e30f;
        for (int e = 0; e < NEXP; e++) m = fmaxf(m, logits[e]);
        float p[NEXP];
        for (int e = 0; e < NEXP; e++) p[e] = expf(logits[e] - m);
        int i0 = 0;
        for (int e = 1; e < NEXP; e++) if (p[e] > p[i0]) i0 = e;
        int i1 = -1;
        for (int e = 0; e < NEXP; e++) {
            if (e == i0) continue;
            if (i1 < 0 || p[e] > p[i1]) i1 = e;
        }
        float s2 = p[i0] + p[i1];
        sel[0] = i0; sel[1] = i1;
        rws[0] = p[i0] / s2; rws[1] = p[i1] / s2;
    }
    if (threadIdx.x < NEXP * NR) g_c[n * NEXP * NR + threadIdx.x] = 0.f;
    __syncthreads();

    int p  = threadIdx.x >> 3;
    int l8 = threadIdx.x & 7;
    int k  = p >> 3;
    int r  = p & 7;
    int e  = sel[k];
    const float* A = lora_A + (size_t)e * HDIM * NR + r;
    float s = 0.f;
    for (int h = l8; h < HDIM; h += 8) s += xs[h] * A[(size_t)h * NR];
    s += __shfl_down_sync(0xffffffffu, s, 4);
    s += __shfl_down_sync(0xffffffffu, s, 2);
    s += __shfl_down_sync(0xffffffffu, s, 1);
    if (l8 == 0) g_c[n * NEXP * NR + e * NR + r] = rws[k] * LSCALE * s;
}

// ---------------------------------------------------------------------------
// Small fp32 SGEMM for LoRA (K=64), writes out with beta=0
// ---------------------------------------------------------------------------
__global__ void __launch_bounds__(256) sgemm128_kernel(
    const float* __restrict__ A, const float* __restrict__ B,
    float* __restrict__ C, int M, int N, int K)
{
    __shared__ float As[8][128];
    __shared__ float Bs[8][128];
    int tid = threadIdx.x;
    int m0 = blockIdx.y * 128, n0 = blockIdx.x * 128;
    int aRow = tid >> 1, aCol = (tid & 1) * 4;
    int bRow = tid >> 5, bCol = (tid & 31) * 4;
    const float* Aptr = A + (size_t)(m0 + aRow) * K + aCol;
    const float* Bptr = B + (size_t)bRow * N + n0 + bCol;
    int ty = tid >> 4, tx = tid & 15;

    float acc[8][8];
    #pragma unroll
    for (int i = 0; i < 8; i++)
        #pragma unroll
        for (int j = 0; j < 8; j++) acc[i][j] = 0.f;

    for (int k0 = 0; k0 < K; k0 += 8) {
        float4 av = *(const float4*)Aptr; Aptr += 8;
        float4 bv = *(const float4*)Bptr; Bptr += (size_t)8 * N;
        As[aCol + 0][aRow] = av.x; As[aCol + 1][aRow] = av.y;
        As[aCol + 2][aRow] = av.z; As[aCol + 3][aRow] = av.w;
        *(float4*)&Bs[bRow][bCol] = bv;
        __syncthreads();
        #pragma unroll
        for (int kk = 0; kk < 8; kk++) {
            float a[8], b[8];
            *(float4*)(a)     = *(const float4*)&As[kk][ty * 8];
            *(float4*)(a + 4) = *(const float4*)&As[kk][ty * 8 + 4];
            *(float4*)(b)     = *(const float4*)&Bs[kk][tx * 8];
            *(float4*)(b + 4) = *(const float4*)&Bs[kk][tx * 8 + 4];
            #pragma unroll
            for (int i = 0; i < 8; i++)
                #pragma unroll
                for (int j = 0; j < 8; j++)
                    acc[i][j] = fmaf(a[i], b[j], acc[i][j]);
        }
        __syncthreads();
    }
    #pragma unroll
    for (int i = 0; i < 8; i++) {
        float* Cr = C + (size_t)(m0 + ty * 8 + i) * N + n0 + tx * 8;
        *(float4*)Cr       = make_float4(acc[i][0], acc[i][1], acc[i][2], acc[i][3]);
        *(float4*)(Cr + 4) = make_float4(acc[i][4], acc[i][5], acc[i][6], acc[i][7]);
    }
}

// ---------------------------------------------------------------------------
// FUSED gate+up GEMM, 128m x 64n CTA tile (occ=2).
// Stage 32KB: A rows 0-127, B1 rows 128-191, B3 rows 192-255.
// Epilogue: a2 = fp16(silu(gate) * up). Raster: groups of 8 n-tiles.
// ---------------------------------------------------------------------------
#define FSTG 32768
#define FUSED_SMEM (3 * FSTG)

__device__ __forceinline__ void issue_stage_gu(
    uint32_t st, const __half* A, const __half* B1, const __half* B3,
    int m0, int n0, int kpos, int K, int lr, int lkc)
{
    #pragma unroll
    for (int rr = 0; rr < 256; rr += 32) {
        int row = lr + rr;
        uint32_t so = row * 128 + ((lkc ^ (row & 7)) << 4);
        const __half* src;
        if (rr < 128)      src = A  + (size_t)(m0 + row) * K;
        else if (rr < 192) src = B1 + (size_t)(n0 + row - 128) * K;
        else               src = B3 + (size_t)(n0 + row - 192) * K;
        CP16(st + so, src + kpos + lkc * 8);
    }
    CP_COMMIT();
}

__global__ void __launch_bounds__(256, 2) gemm_gateup_kernel(
    const __half* __restrict__ A, const __half* __restrict__ B1,
    const __half* __restrict__ B3, __half* __restrict__ oA2, int K)
{
    extern __shared__ __align__(1024) char smem[];
    uint32_t sb = smem_u32(smem);
    int tid = threadIdx.x;
    int wid = tid >> 5, lane = tid & 31;
    int wm = wid >> 2, wn = wid & 3;

    int lin = blockIdx.y * gridDim.x + blockIdx.x;
    int gs  = 8 * gridDim.y;
    int g   = lin / gs, r = lin - g * gs;
    int m0  = (r >> 3) * 128;
    int n0  = (g * 8 + (r & 7)) * 64;

    int NT = K >> 6;
    int lr = tid >> 3, lkc = tid & 7;

    int laneM  = lane & 15;
    int kHalfA = lane >> 4;
    int aSw    = laneM & 7;
    uint32_t rowOffA[4];
    #pragma unroll
    for (int tm = 0; tm < 4; tm++)
        rowOffA[tm] = (uint32_t)(wm * 64 + tm * 16 + laneM) * 128;
    int l7     = lane & 7;
    int kHalfB = (lane >> 3) & 1;
    uint32_t rowB = (uint32_t)(wn * 16 + ((lane >> 4) & 1) * 8 + l7) * 128;

    float accG[4][2][4], accU[4][2][4];
    #pragma unroll
    for (int i = 0; i < 4; i++)
        #pragma unroll
        for (int j = 0; j < 2; j++)
            #pragma unroll
            for (int q = 0; q < 4; q++) { accG[i][j][q] = 0.f; accU[i][j][q] = 0.f; }

    issue_stage_gu(sb,        A, B1, B3, m0, n0, 0,  K, lr, lkc);
    issue_stage_gu(sb + FSTG, A, B1, B3, m0, n0, 64, K, lr, lkc);

    for (int kt = 0; kt < NT; kt++) {
        CP_WAIT1();
        __syncthreads();
        if (kt + 2 < NT)
            issue_stage_gu(sb + ((kt + 2) % 3) * FSTG, A, B1, B3,
                           m0, n0, (kt + 2) << 6, K, lr, lkc);
        else
            CP_COMMIT();

        uint32_t st = sb + (kt % 3) * FSTG;
        #pragma unroll
        for (int kk = 0; kk < 4; kk++) {
            uint32_t ah[4][4], b1f[4], b3f[4];
            uint32_t chA = (uint32_t)(((kk * 2 + kHalfA) ^ aSw) << 4);
            #pragma unroll
            for (int tm = 0; tm < 4; tm++)
                LDSM4(ah[tm][0], ah[tm][1], ah[tm][2], ah[tm][3], st + rowOffA[tm] + chA);
            uint32_t chB = (uint32_t)(((kk * 2 + kHalfB) ^ l7) << 4);
            LDSM4(b1f[0], b1f[1], b1f[2], b1f[3], st + 16384 + rowB + chB);
            LDSM4(b3f[0], b3f[1], b3f[2], b3f[3], st + 24576 + rowB + chB);
            #pragma unroll
            for (int tm = 0; tm < 4; tm++)
                #pragma unroll
                for (int tn = 0; tn < 2; tn++) {
                    MMA_F16(accG[tm][tn], ah[tm][0], ah[tm][1], ah[tm][2], ah[tm][3],
                            b1f[2 * tn], b1f[2 * tn + 1]);
                    MMA_F16(accU[tm][tn], ah[tm][0], ah[tm][1], ah[tm][2], ah[tm][3],
                            b3f[2 * tn], b3f[2 * tn + 1]);
                }
        }
    }

    int g2 = lane >> 2, q2 = (lane & 3) * 2;
    size_t Nt = (size_t)gridDim.x * 64;
    #pragma unroll
    for (int tm = 0; tm < 4; tm++) {
        #pragma unroll
        for (int tn = 0; tn < 2; tn++) {
            int mg = m0 + wm * 64 + tm * 16 + g2;
            int cg = n0 + wn * 16 + tn * 8 + q2;
            size_t o0 = (size_t)mg * Nt + cg;
            size_t o1 = o0 + 8 * Nt;
            float* gg = accG[tm][tn];
            float* uu = accU[tm][tn];
            float v0 = gg[0] / (1.f + __expf(-gg[0])) * uu[0];
            float v1 = gg[1] / (1.f + __expf(-gg[1])) * uu[1];
            float v2 = gg[2] / (1.f + __expf(-gg[2])) * uu[2];
            float v3 = gg[3] / (1.f + __expf(-gg[3])) * uu[3];
            *(__half2*)(oA2 + o0) = __floats2half2_rn(v0, v1);
            *(__half2*)(oA2 + o1) = __floats2half2_rn(v2, v3);
        }
    }
}

// ---------------------------------------------------------------------------
// Down-projection fp16 GEMM (accumulate onto out): C += A @ B^T
// 128x128 tile, occ=2, raster swizzle. (round-7 config — known good)
// ---------------------------------------------------------------------------
#define STAGE_BYTES 32768
#define GEMM_SMEM   (3 * STAGE_BYTES)

__device__ __forceinline__ void issue_stage_f16(
    uint32_t st, const __half* A, const __half* B,
    int m0, int n0, int kpos, int K, int lr, int lkc)
{
    #pragma unroll
    for (int rr = 0; rr < 128; rr += 32) {
        int row = lr + rr;
        uint32_t so = row * 128 + ((lkc ^ (row & 7)) << 4);
        size_t ga = (size_t)(m0 + row) * K + kpos + lkc * 8;
        size_t gb = (size_t)(n0 + row) * K + kpos + lkc * 8;
        CP16(st + so,         A + ga);
        CP16(st + 16384 + so, B + gb);
    }
    CP_COMMIT();
}

__global__ void __launch_bounds__(256, 2) gemm_down_kernel(
    const __half* __restrict__ A, const __half* __restrict__ B,
    float* __restrict__ C, int K)
{
    extern __shared__ __align__(1024) char smem[];
    uint32_t sb = smem_u32(smem);
    int tid = threadIdx.x;
    int wid = tid >> 5, lane = tid & 31;
    int wm = wid >> 2, wn = wid & 3;

    int lin = blockIdx.y * gridDim.x + blockIdx.x;
    int gs  = 8 * gridDim.y;
    int g   = lin / gs, r = lin - g * gs;
    int m0  = (r >> 3) * 128;
    int n0  = (g * 8 + (r & 7)) * 128;

    int NT = K >> 6;
    int lr = tid >> 3, lkc = tid & 7;

    int laneM  = lane & 15;
    int kHalfA = lane >> 4;
    int aSw    = laneM & 7;
    uint32_t rowOffA[4];
    #pragma unroll
    for (int tm = 0; tm < 4; tm++)
        rowOffA[tm] = (uint32_t)(wm * 64 + tm * 16 + laneM) * 128;
    int l7     = lane & 7;
    int kHalfB = (lane >> 3) & 1;
    uint32_t rowOffB[2];
    #pragma unroll
    for (int pr = 0; pr < 2; pr++)
        rowOffB[pr] = (uint32_t)(wn * 32 + pr * 16 + ((lane >> 4) & 1) * 8 + l7) * 128;

    float acc[4][4][4];
    #pragma unroll
    for (int i = 0; i < 4; i++)
        #pragma unroll
        for (int j = 0; j < 4; j++)
            #pragma unroll
            for (int q = 0; q < 4; q++) acc[i][j][q] = 0.f;

    issue_stage_f16(sb,               A, B, m0, n0, 0,  K, lr, lkc);
    issue_stage_f16(sb + STAGE_BYTES, A, B, m0, n0, 64, K, lr, lkc);

    for (int kt = 0; kt < NT; kt++) {
        CP_WAIT1();
        __syncthreads();
        if (kt + 2 < NT)
            issue_stage_f16(sb + ((kt + 2) % 3) * STAGE_BYTES, A, B,
                            m0, n0, (kt + 2) << 6, K, lr, lkc);
        else
            CP_COMMIT();

        uint32_t st = sb + (kt % 3) * STAGE_BYTES;
        #pragma unroll
        for (int kk = 0; kk < 4; kk++) {
            uint32_t ah[4][4], bh[8];
            uint32_t chA = (uint32_t)(((kk * 2 + kHalfA) ^ aSw) << 4);
            #pragma unroll
            for (int tm = 0; tm < 4; tm++)
                LDSM4(ah[tm][0], ah[tm][1], ah[tm][2], ah[tm][3], st + rowOffA[tm] + chA);
            uint32_t chB = (uint32_t)(((kk * 2 + kHalfB) ^ l7) << 4);
            LDSM4(bh[0], bh[1], bh[2], bh[3], st + 16384 + rowOffB[0] + chB);
            LDSM4(bh[4], bh[5], bh[6], bh[7], st + 16384 + rowOffB[1] + chB);
            #pragma unroll
            for (int tm = 0; tm < 4; tm++)
                #pragma unroll
                for (int tn = 0; tn < 4; tn++)
                    MMA_F16(acc[tm][tn], ah[tm][0], ah[tm][1], ah[tm][2], ah[tm][3],
                            bh[2 * tn], bh[2 * tn + 1]);
        }
    }

    int g2 = lane >> 2, q2 = (lane & 3) * 2;
    size_t Nt = (size_t)gridDim.x * 128;
    #pragma unroll
    for (int tm = 0; tm < 4; tm++) {
        #pragma unroll
        for (int tn = 0; tn < 4; tn++) {
            int mg = m0 + wm * 64 + tm * 16 + g2;
            int cg = n0 + wn * 32 + tn * 8 + q2;
            size_t o0 = (size_t)mg * Nt + cg;
            size_t o1 = o0 + 8 * Nt;
            float* a = acc[tm][tn];
            float2 c0 = *(const float2*)(C + o0);
            float2 c1 = *(const float2*)(C + o1);
            c0.x += a[0]; c0.y += a[1];
            c1.x += a[2]; c1.y += a[3];
            *(float2*)(C + o0) = c0;
            *(float2*)(C + o1) = c1;
        }
    }
}

// ---------------------------------------------------------------------------
extern "C" void kernel_launch(void* const* d_in, const int* in_sizes, int n_in,
                              void* d_out, int out_size)
{
    const float* x        = (const float*)d_in[0];
    const float* router_w = (const float*)d_in[1];
    const float* w1       = (const float*)d_in[2];
    const float* w2       = (const float*)d_in[3];
    const float* w3       = (const float*)d_in[4];
    const float* lora_A   = (const float*)d_in[5];
    const float* lora_B   = (const float*)d_in[6];
    float* out = (float*)d_out;

    static bool init_done = false;
    static float *cc;
    static __half *xh, *b1, *b3, *b2, *a2;
    if (!init_done) {
        cudaGetSymbolAddress((void**)&cc, g_c);
        cudaGetSymbolAddress((void**)&xh, g_xh);
        cudaGetSymbolAddress((void**)&b1, g_b1);
        cudaGetSymbolAddress((void**)&b3, g_b3);
        cudaGetSymbolAddress((void**)&b2, g_b2);
        cudaGetSymbolAddress((void**)&a2, g_a2);
        cudaFuncSetAttribute(gemm_gateup_kernel,
                             cudaFuncAttributeMaxDynamicSharedMemorySize, FUSED_SMEM);
        cudaFuncSetAttribute(gemm_down_kernel,
                             cudaFuncAttributeMaxDynamicSharedMemorySize, GEMM_SMEM);
        init_done = true;
    }

    float* logits_out = nullptr;
    if ((size_t)out_size >= (size_t)NTOK * HDIM + (size_t)NTOK * NEXP)
        logits_out = out + (size_t)NTOK * HDIM;

    // router + LoRA coefficients + x fp16 conversion (folded)
    router_lora_kernel<<<NTOK, 128>>>(x, router_w, lora_A, logits_out);

    // all three weight transposes in one launch
    transpose_all_kernel<<<dim3(28672, 3), 256>>>(w1, w3, w2, b1, b3, b2);

    // LoRA GEMM initializes out (beta=0)
    sgemm128_kernel<<<dim3(HDIM / 128, NTOK / 128), 256>>>(cc, lora_B, out, NTOK, HDIM, NEXP * NR);

    // Fused gate+up: a2 = fp16(silu(x@w1) * (x@w3)), 128x64 tiles
    gemm_gateup_kernel<<<dim3(FDIM / 64, NTOK / 128), 256, FUSED_SMEM>>>(
        xh, b1, b3, a2, HDIM);

    // Down-proj: out += a2 @ w2 (128x128 tiles — round-7 config)
    gemm_down_kernel<<<dim3(HDIM / 128, NTOK / 128), 256, GEMM_SMEM>>>(
        a2, b2, out, FDIM);
}

// round 10
// speedup vs baseline: 1.7193x; 1.0511x over previous
#include <cuda_runtime.h>
#include <cuda_fp16.h>
#include <cstdint>
#include <math.h>

#define NTOK 4096
#define HDIM 4096
#define FDIM 14336
#define NEXP 8
#define NR   8
#define LSCALE 2.0f

// ---------------------------------------------------------------------------
// Scratch (__device__ globals; allocation-free rule)
// ---------------------------------------------------------------------------
__device__ __half g_xh[(size_t)NTOK * HDIM];   // x as fp16 [N,H]
__device__ __half g_b1[(size_t)FDIM * HDIM];   // w1^T [F,H] fp16
__device__ __half g_b3[(size_t)FDIM * HDIM];   // w3^T [F,H] fp16
__device__ __half g_b2[(size_t)HDIM * FDIM];   // w2^T [H,F] fp16
__device__ __half g_a2[(size_t)NTOK * FDIM];   // silu(gate)*up fp16 [N,F]
__device__ float  g_c[NTOK * NEXP * NR];       // LoRA coefficients

// ---------------------------------------------------------------------------
// Asm helpers (sm_80-level features; legal on plain sm_103 target)
// ---------------------------------------------------------------------------
__device__ __forceinline__ uint32_t smem_u32(const void* p) {
    uint32_t a;
    asm("{ .reg .u64 t; cvta.to.shared.u64 t, %1; cvt.u32.u64 %0, t; }" : "=r"(a) : "l"(p));
    return a;
}

#define CP16(dst, src) \
    asm volatile("cp.async.cg.shared.global [%0], [%1], 16;" :: "r"(dst), "l"(src))
#define CP_COMMIT() asm volatile("cp.async.commit_group;" ::: "memory")
#define CP_WAIT1()  asm volatile("cp.async.wait_group 1;" ::: "memory")

#define LDSM4(r0, r1, r2, r3, a) \
    asm volatile("ldmatrix.sync.aligned.m8n8.x4.shared.b16 {%0,%1,%2,%3}, [%4];" \
        : "=r"(r0), "=r"(r1), "=r"(r2), "=r"(r3) : "r"(a))

#define MMA_F16(c, a0, a1, a2, a3, b0, b1) \
    asm volatile("mma.sync.aligned.m16n8k16.row.col.f32.f16.f16.f32 " \
        "{%0,%1,%2,%3}, {%4,%5,%6,%7}, {%8,%9}, {%0,%1,%2,%3};" \
        : "+f"((c)[0]), "+f"((c)[1]), "+f"((c)[2]), "+f"((c)[3]) \
        : "r"(a0), "r"(a1), "r"(a2), "r"(a3), "r"(b0), "r"(b1))

// ---------------------------------------------------------------------------
// Merged transpose: one launch converts w1,w3,w2 (fp32 [K,N] -> fp16 [N,K]).
// ---------------------------------------------------------------------------
__global__ void __launch_bounds__(256) transpose_all_kernel(
    const float* __restrict__ w1, const float* __restrict__ w3,
    const float* __restrict__ w2,
    __half* __restrict__ b1, __half* __restrict__ b3, __half* __restrict__ b2)
{
    const float* W;
    __half* out;
    int K, N, nBlk;
    if (blockIdx.y == 0)      { W = w1; out = b1; K = HDIM; N = FDIM; nBlk = FDIM / 32; }
    else if (blockIdx.y == 1) { W = w3; out = b3; K = HDIM; N = FDIM; nBlk = FDIM / 32; }
    else                      { W = w2; out = b2; K = FDIM; N = HDIM; nBlk = HDIM / 32; }

    int b  = blockIdx.x;
    int n0 = (b % nBlk) * 32;
    int k0 = (b / nBlk) * 64;

    __shared__ float t[64][33];
    int tx = threadIdx.x & 31, ty = threadIdx.x >> 5;   // 32 x 8
    #pragma unroll
    for (int j = 0; j < 8; j++)
        t[ty + 8 * j][tx] = W[(size_t)(k0 + ty + 8 * j) * N + n0 + tx];
    __syncthreads();
    #pragma unroll
    for (int j = 0; j < 4; j++) {
        int n = ty + 8 * j;     // 0..31
        __half2 h = __floats2half2_rn(t[2 * tx][n], t[2 * tx + 1][n]);
        *(__half2*)(out + (size_t)(n0 + n) * K + k0 + 2 * tx) = h;
    }
}

// ---------------------------------------------------------------------------
// Router + LoRA coefficients + x fp16 conversion.
// LoRA-A access rewritten: each warp owns (selected-expert, h-half); each lane
// loads the full 8-rank row for its h (two float4s, warp = 1KB contiguous).
// ---------------------------------------------------------------------------
__global__ void __launch_bounds__(128) router_lora_kernel(
    const float* __restrict__ x, const float* __restrict__ router_w,
    const float* __restrict__ lora_A, float* __restrict__ logits_out)
{
    int n = blockIdx.x;
    __shared__ float xs[HDIM];
    __shared__ float logits[NEXP];
    __shared__ int   sel[2];
    __shared__ float rws[2];
    __shared__ float red[4][32][NR];   // per-warp per-lane rank partials (4KB)

    const float* xr = x + (size_t)n * HDIM;
    for (int i = threadIdx.x; i < HDIM / 4; i += blockDim.x)
        ((float4*)xs)[i] = ((const float4*)xr)[i];
    __syncthreads();

    // fp16 conversion of x (same rounding intrinsic as before)
    {
        __half* xo = g_xh + (size_t)n * HDIM;
        for (int i = threadIdx.x; i < HDIM / 2; i += blockDim.x)
            *(__half2*)(xo + 2 * i) = __floats2half2_rn(xs[2 * i], xs[2 * i + 1]);
    }

    int wid = threadIdx.x >> 5, lane = threadIdx.x & 31;
    for (int e = wid; e < NEXP; e += 4) {
        const float* wr = router_w + (size_t)e * HDIM;
        float s = 0.f;
        for (int h = lane; h < HDIM; h += 32) s += xs[h] * wr[h];
        #pragma unroll
        for (int o = 16; o; o >>= 1) s += __shfl_down_sync(0xffffffffu, s, o);
        if (lane == 0) {
            logits[e] = s;
            if (logits_out) logits_out[(size_t)n * NEXP + e] = s;
        }
    }
    __syncthreads();

    if (threadIdx.x == 0) {
        float m = -1e30f;
        for (int e = 0; e < NEXP; e++) m = fmaxf(m, logits[e]);
        float p[NEXP];
        for (int e = 0; e < NEXP; e++) p[e] = expf(logits[e] - m);
        int i0 = 0;
        for (int e = 1; e < NEXP; e++) if (p[e] > p[i0]) i0 = e;
        int i1 = -1;
        for (int e = 0; e < NEXP; e++) {
            if (e == i0) continue;
            if (i1 < 0 || p[e] > p[i1]) i1 = e;
        }
        float s2 = p[i0] + p[i1];
        sel[0] = i0; sel[1] = i1;
        rws[0] = p[i0] / s2; rws[1] = p[i1] / s2;
    }
    if (threadIdx.x < NEXP * NR) g_c[n * NEXP * NR + threadIdx.x] = 0.f;
    __syncthreads();

    // ---- coalesced LoRA-A projection ----
    // warp -> (expert slot k = wid>>1, h-half = wid&1)
    {
        int k    = wid >> 1;                    // 0..1 (selected expert slot)
        int half = wid & 1;                     // 0..1 (h range half)
        int e    = sel[k];
        const float* A = lora_A + (size_t)e * HDIM * NR;
        float acc[NR];
        #pragma unroll
        for (int r = 0; r < NR; r++) acc[r] = 0.f;
        int h0 = half * (HDIM / 2);
        for (int it = 0; it < (HDIM / 2) / 32; it++) {
            int h = h0 + it * 32 + lane;
            const float4* ap = (const float4*)(A + (size_t)h * NR);
            float4 a0 = ap[0];
            float4 a1 = ap[1];
            float xv = xs[h];
            acc[0] += xv * a0.x; acc[1] += xv * a0.y;
            acc[2] += xv * a0.z; acc[3] += xv * a0.w;
            acc[4] += xv * a1.x; acc[5] += xv * a1.y;
            acc[6] += xv * a1.z; acc[7] += xv * a1.w;
        }
        #pragma unroll
        for (int r = 0; r < NR; r++) red[wid][lane][r] = acc[r];
    }
    __syncthreads();

    if (threadIdx.x < 2 * NR) {
        int k = threadIdx.x >> 3;      // expert slot
        int r = threadIdx.x & 7;       // rank
        float s = 0.f;
        #pragma unroll
        for (int w = 0; w < 2; w++)
            for (int l = 0; l < 32; l++)
                s += red[2 * k + w][l][r];
        g_c[n * NEXP * NR + sel[k] * NR + r] = rws[k] * LSCALE * s;
    }
}

// ---------------------------------------------------------------------------
// Small fp32 SGEMM for LoRA (K=64), writes out with beta=0
// ---------------------------------------------------------------------------
__global__ void __launch_bounds__(256) sgemm128_kernel(
    const float* __restrict__ A, const float* __restrict__ B,
    float* __restrict__ C, int M, int N, int K)
{
    __shared__ float As[8][128];
    __shared__ float Bs[8][128];
    int tid = threadIdx.x;
    int m0 = blockIdx.y * 128, n0 = blockIdx.x * 128;
    int aRow = tid >> 1, aCol = (tid & 1) * 4;
    int bRow = tid >> 5, bCol = (tid & 31) * 4;
    const float* Aptr = A + (size_t)(m0 + aRow) * K + aCol;
    const float* Bptr = B + (size_t)bRow * N + n0 + bCol;
    int ty = tid >> 4, tx = tid & 15;

    float acc[8][8];
    #pragma unroll
    for (int i = 0; i < 8; i++)
        #pragma unroll
        for (int j = 0; j < 8; j++) acc[i][j] = 0.f;

    for (int k0 = 0; k0 < K; k0 += 8) {
        float4 av = *(const float4*)Aptr; Aptr += 8;
        float4 bv = *(const float4*)Bptr; Bptr += (size_t)8 * N;
        As[aCol + 0][aRow] = av.x; As[aCol + 1][aRow] = av.y;
        As[aCol + 2][aRow] = av.z; As[aCol + 3][aRow] = av.w;
        *(float4*)&Bs[bRow][bCol] = bv;
        __syncthreads();
        #pragma unroll
        for (int kk = 0; kk < 8; kk++) {
            float a[8], b[8];
            *(float4*)(a)     = *(const float4*)&As[kk][ty * 8];
            *(float4*)(a + 4) = *(const float4*)&As[kk][ty * 8 + 4];
            *(float4*)(b)     = *(const float4*)&Bs[kk][tx * 8];
            *(float4*)(b + 4) = *(const float4*)&Bs[kk][tx * 8 + 4];
            #pragma unroll
            for (int i = 0; i < 8; i++)
                #pragma unroll
                for (int j = 0; j < 8; j++)
                    acc[i][j] = fmaf(a[i], b[j], acc[i][j]);
        }
        __syncthreads();
    }
    #pragma unroll
    for (int i = 0; i < 8; i++) {
        float* Cr = C + (size_t)(m0 + ty * 8 + i) * N + n0 + tx * 8;
        *(float4*)Cr       = make_float4(acc[i][0], acc[i][1], acc[i][2], acc[i][3]);
        *(float4*)(Cr + 4) = make_float4(acc[i][4], acc[i][5], acc[i][6], acc[i][7]);
    }
}

// ---------------------------------------------------------------------------
// FUSED gate+up GEMM, 128m x 64n CTA tile (occ=2).
// ---------------------------------------------------------------------------
#define FSTG 32768
#define FUSED_SMEM (3 * FSTG)

__device__ __forceinline__ void issue_stage_gu(
    uint32_t st, const __half* A, const __half* B1, const __half* B3,
    int m0, int n0, int kpos, int K, int lr, int lkc)
{
    #pragma unroll
    for (int rr = 0; rr < 256; rr += 32) {
        int row = lr + rr;
        uint32_t so = row * 128 + ((lkc ^ (row & 7)) << 4);
        const __half* src;
        if (rr < 128)      src = A  + (size_t)(m0 + row) * K;
        else if (rr < 192) src = B1 + (size_t)(n0 + row - 128) * K;
        else               src = B3 + (size_t)(n0 + row - 192) * K;
        CP16(st + so, src + kpos + lkc * 8);
    }
    CP_COMMIT();
}

__global__ void __launch_bounds__(256, 2) gemm_gateup_kernel(
    const __half* __restrict__ A, const __half* __restrict__ B1,
    const __half* __restrict__ B3, __half* __restrict__ oA2, int K)
{
    extern __shared__ __align__(1024) char smem[];
    uint32_t sb = smem_u32(smem);
    int tid = threadIdx.x;
    int wid = tid >> 5, lane = tid & 31;
    int wm = wid >> 2, wn = wid & 3;

    int lin = blockIdx.y * gridDim.x + blockIdx.x;
    int gs  = 8 * gridDim.y;
    int g   = lin / gs, r = lin - g * gs;
    int m0  = (r >> 3) * 128;
    int n0  = (g * 8 + (r & 7)) * 64;

    int NT = K >> 6;
    int lr = tid >> 3, lkc = tid & 7;

    int laneM  = lane & 15;
    int kHalfA = lane >> 4;
    int aSw    = laneM & 7;
    uint32_t rowOffA[4];
    #pragma unroll
    for (int tm = 0; tm < 4; tm++)
        rowOffA[tm] = (uint32_t)(wm * 64 + tm * 16 + laneM) * 128;
    int l7     = lane & 7;
    int kHalfB = (lane >> 3) & 1;
    uint32_t rowB = (uint32_t)(wn * 16 + ((lane >> 4) & 1) * 8 + l7) * 128;

    float accG[4][2][4], accU[4][2][4];
    #pragma unroll
    for (int i = 0; i < 4; i++)
        #pragma unroll
        for (int j = 0; j < 2; j++)
            #pragma unroll
            for (int q = 0; q < 4; q++) { accG[i][j][q] = 0.f; accU[i][j][q] = 0.f; }

    issue_stage_gu(sb,        A, B1, B3, m0, n0, 0,  K, lr, lkc);
    issue_stage_gu(sb + FSTG, A, B1, B3, m0, n0, 64, K, lr, lkc);

    for (int kt = 0; kt < NT; kt++) {
        CP_WAIT1();
        __syncthreads();
        if (kt + 2 < NT)
            issue_stage_gu(sb + ((kt + 2) % 3) * FSTG, A, B1, B3,
                           m0, n0, (kt + 2) << 6, K, lr, lkc);
        else
            CP_COMMIT();

        uint32_t st = sb + (kt % 3) * FSTG;
        #pragma unroll
        for (int kk = 0; kk < 4; kk++) {
            uint32_t ah[4][4], b1f[4], b3f[4];
            uint32_t chA = (uint32_t)(((kk * 2 + kHalfA) ^ aSw) << 4);
            #pragma unroll
            for (int tm = 0; tm < 4; tm++)
                LDSM4(ah[tm][0], ah[tm][1], ah[tm][2], ah[tm][3], st + rowOffA[tm] + chA);
            uint32_t chB = (uint32_t)(((kk * 2 + kHalfB) ^ l7) << 4);
            LDSM4(b1f[0], b1f[1], b1f[2], b1f[3], st + 16384 + rowB + chB);
            LDSM4(b3f[0], b3f[1], b3f[2], b3f[3], st + 24576 + rowB + chB);
            #pragma unroll
            for (int tm = 0; tm < 4; tm++)
                #pragma unroll
                for (int tn = 0; tn < 2; tn++) {
                    MMA_F16(accG[tm][tn], ah[tm][0], ah[tm][1], ah[tm][2], ah[tm][3],
                            b1f[2 * tn], b1f[2 * tn + 1]);
                    MMA_F16(accU[tm][tn], ah[tm][0], ah[tm][1], ah[tm][2], ah[tm][3],
                            b3f[2 * tn], b3f[2 * tn + 1]);
                }
        }
    }

    int g2 = lane >> 2, q2 = (lane & 3) * 2;
    size_t Nt = (size_t)gridDim.x * 64;
    #pragma unroll
    for (int tm = 0; tm < 4; tm++) {
        #pragma unroll
        for (int tn = 0; tn < 2; tn++) {
            int mg = m0 + wm * 64 + tm * 16 + g2;
            int cg = n0 + wn * 16 + tn * 8 + q2;
            size_t o0 = (size_t)mg * Nt + cg;
            size_t o1 = o0 + 8 * Nt;
            float* gg = accG[tm][tn];
            float* uu = accU[tm][tn];
            float v0 = gg[0] / (1.f + __expf(-gg[0])) * uu[0];
            float v1 = gg[1] / (1.f + __expf(-gg[1])) * uu[1];
            float v2 = gg[2] / (1.f + __expf(-gg[2])) * uu[2];
            float v3 = gg[3] / (1.f + __expf(-gg[3])) * uu[3];
            *(__half2*)(oA2 + o0) = __floats2half2_rn(v0, v1);
            *(__half2*)(oA2 + o1) = __floats2half2_rn(v2, v3);
        }
    }
}

// ---------------------------------------------------------------------------
// Down-projection fp16 GEMM (accumulate onto out): C += A @ B^T
// 128x128 tile, occ=2, raster swizzle.
// ---------------------------------------------------------------------------
#define STAGE_BYTES 32768
#define GEMM_SMEM   (3 * STAGE_BYTES)

__device__ __forceinline__ void issue_stage_f16(
    uint32_t st, const __half* A, const __half* B,
    int m0, int n0, int kpos, int K, int lr, int lkc)
{
    #pragma unroll
    for (int rr = 0; rr < 128; rr += 32) {
        int row = lr + rr;
        uint32_t so = row * 128 + ((lkc ^ (row & 7)) << 4);
        size_t ga = (size_t)(m0 + row) * K + kpos + lkc * 8;
        size_t gb = (size_t)(n0 + row) * K + kpos + lkc * 8;
        CP16(st + so,         A + ga);
        CP16(st + 16384 + so, B + gb);
    }
    CP_COMMIT();
}

__global__ void __launch_bounds__(256, 2) gemm_down_kernel(
    const __half* __restrict__ A, const __half* __restrict__ B,
    float* __restrict__ C, int K)
{
    extern __shared__ __align__(1024) char smem[];
    uint32_t sb = smem_u32(smem);
    int tid = threadIdx.x;
    int wid = tid >> 5, lane = tid & 31;
    int wm = wid >> 2, wn = wid & 3;

    int lin = blockIdx.y * gridDim.x + blockIdx.x;
    int gs  = 8 * gridDim.y;
    int g   = lin / gs, r = lin - g * gs;
    int m0  = (r >> 3) * 128;
    int n0  = (g * 8 + (r & 7)) * 128;

    int NT = K >> 6;
    int lr = tid >> 3, lkc = tid & 7;

    int laneM  = lane & 15;
    int kHalfA = lane >> 4;
    int aSw    = laneM & 7;
    uint32_t rowOffA[4];
    #pragma unroll
    for (int tm = 0; tm < 4; tm++)
        rowOffA[tm] = (uint32_t)(wm * 64 + tm * 16 + laneM) * 128;
    int l7     = lane & 7;
    int kHalfB = (lane >> 3) & 1;
    uint32_t rowOffB[2];
    #pragma unroll
    for (int pr = 0; pr < 2; pr++)
        rowOffB[pr] = (uint32_t)(wn * 32 + pr * 16 + ((lane >> 4) & 1) * 8 + l7) * 128;

    float acc[4][4][4];
    #pragma unroll
    for (int i = 0; i < 4; i++)
        #pragma unroll
        for (int j = 0; j < 4; j++)
            #pragma unroll
            for (int q = 0; q < 4; q++) acc[i][j][q] = 0.f;

    issue_stage_f16(sb,               A, B, m0, n0, 0,  K, lr, lkc);
    issue_stage_f16(sb + STAGE_BYTES, A, B, m0, n0, 64, K, lr, lkc);

    for (int kt = 0; kt < NT; kt++) {
        CP_WAIT1();
        __syncthreads();
        if (kt + 2 < NT)
            issue_stage_f16(sb + ((kt + 2) % 3) * STAGE_BYTES, A, B,
                            m0, n0, (kt + 2) << 6, K, lr, lkc);
        else
            CP_COMMIT();

        uint32_t st = sb + (kt % 3) * STAGE_BYTES;
        #pragma unroll
        for (int kk = 0; kk < 4; kk++) {
            uint32_t ah[4][4], bh[8];
            uint32_t chA = (uint32_t)(((kk * 2 + kHalfA) ^ aSw) << 4);
            #pragma unroll
            for (int tm = 0; tm < 4; tm++)
                LDSM4(ah[tm][0], ah[tm][1], ah[tm][2], ah[tm][3], st + rowOffA[tm] + chA);
            uint32_t chB = (uint32_t)(((kk * 2 + kHalfB) ^ l7) << 4);
            LDSM4(bh[0], bh[1], bh[2], bh[3], st + 16384 + rowOffB[0] + chB);
            LDSM4(bh[4], bh[5], bh[6], bh[7], st + 16384 + rowOffB[1] + chB);
            #pragma unroll
            for (int tm = 0; tm < 4; tm++)
                #pragma unroll
                for (int tn = 0; tn < 4; tn++)
                    MMA_F16(acc[tm][tn], ah[tm][0], ah[tm][1], ah[tm][2], ah[tm][3],
                            bh[2 * tn], bh[2 * tn + 1]);
        }
    }

    int g2 = lane >> 2, q2 = (lane & 3) * 2;
    size_t Nt = (size_t)gridDim.x * 128;
    #pragma unroll
    for (int tm = 0; tm < 4; tm++) {
        #pragma unroll
        for (int tn = 0; tn < 4; tn++) {
            int mg = m0 + wm * 64 + tm * 16 + g2;
            int cg = n0 + wn * 32 + tn * 8 + q2;
            size_t o0 = (size_t)mg * Nt + cg;
            size_t o1 = o0 + 8 * Nt;
            float* a = acc[tm][tn];
            float2 c0 = *(const float2*)(C + o0);
            float2 c1 = *(const float2*)(C + o1);
            c0.x += a[0]; c0.y += a[1];
            c1.x += a[2]; c1.y += a[3];
            *(float2*)(C + o0) = c0;
            *(float2*)(C + o1) = c1;
        }
    }
}

// ---------------------------------------------------------------------------
extern "C" void kernel_launch(void* const* d_in, const int* in_sizes, int n_in,
                              void* d_out, int out_size)
{
    const float* x        = (const float*)d_in[0];
    const float* router_w = (const float*)d_in[1];
    const float* w1       = (const float*)d_in[2];
    const float* w2       = (const float*)d_in[3];
    const float* w3       = (const float*)d_in[4];
    const float* lora_A   = (const float*)d_in[5];
    const float* lora_B   = (const float*)d_in[6];
    float* out = (float*)d_out;

    static bool init_done = false;
    static float *cc;
    static __half *xh, *b1, *b3, *b2, *a2;
    if (!init_done) {
        cudaGetSymbolAddress((void**)&cc, g_c);
        cudaGetSymbolAddress((void**)&xh, g_xh);
        cudaGetSymbolAddress((void**)&b1, g_b1);
        cudaGetSymbolAddress((void**)&b3, g_b3);
        cudaGetSymbolAddress((void**)&b2, g_b2);
        cudaGetSymbolAddress((void**)&a2, g_a2);
        cudaFuncSetAttribute(gemm_gateup_kernel,
                             cudaFuncAttributeMaxDynamicSharedMemorySize, FUSED_SMEM);
        cudaFuncSetAttribute(gemm_down_kernel,
                             cudaFuncAttributeMaxDynamicSharedMemorySize, GEMM_SMEM);
        init_done = true;
    }

    float* logits_out = nullptr;
    if ((size_t)out_size >= (size_t)NTOK * HDIM + (size_t)NTOK * NEXP)
        logits_out = out + (size_t)NTOK * HDIM;

    // router + LoRA coefficients + x fp16 conversion
    router_lora_kernel<<<NTOK, 128>>>(x, router_w, lora_A, logits_out);

    // all three weight transposes in one launch
    transpose_all_kernel<<<dim3(28672, 3), 256>>>(w1, w3, w2, b1, b3, b2);

    // LoRA GEMM initializes out (beta=0)
    sgemm128_kernel<<<dim3(HDIM / 128, NTOK / 128), 256>>>(cc, lora_B, out, NTOK, HDIM, NEXP * NR);

    // Fused gate+up: a2 = fp16(silu(x@w1) * (x@w3)), 128x64 tiles
    gemm_gateup_kernel<<<dim3(FDIM / 64, NTOK / 128), 256, FUSED_SMEM>>>(
        xh, b1, b3, a2, HDIM);

    // Down-proj: out += a2 @ w2 (128x128 tiles)
    gemm_down_kernel<<<dim3(HDIM / 128, NTOK / 128), 256, GEMM_SMEM>>>(
        a2, b2, out, FDIM);
}